// round 9
// baseline (speedup 1.0000x reference)
#include <cuda_runtime.h>
#include <cstdint>

#define T_STEPS 512
#define B_SZ    256
#define EMB_D   128
#define HID_D   256
#define OUT_D   64
#define K_TOT   384
#define KPAIRS  192            // K_TOT/2

#define NT      256
#define N_UG    8              // unit groups: 32 units (128 gate rows) each
#define N_BG    16             // batch groups: 16 batches each
#define NB      (N_UG * N_BG)  // 128 CTAs
#define BB_CTA  16             // batches per CTA
#define WROWS   128            // gate rows per CTA
#define APITCH  388            // floats; 388 % 16 == 4 -> conflict-free A rows

typedef unsigned long long u64;

// ---------------- device scratch ------------------------------------------
__device__ float g_hbuf[2][B_SZ][HID_D];
__device__ float g_last[B_SZ][HID_D];
__device__ int   g_idx[B_SZ];
// padded barrier state: one 128B slot per group (16 groups)
__device__ unsigned g_bsense[N_BG * 32];
__device__ unsigned g_bcount[N_BG * 32];

// ---------------- f32x2 helpers -------------------------------------------
__device__ __forceinline__ u64 ffma2(u64 a, u64 b, u64 c) {
    u64 d;
    asm("fma.rn.f32x2 %0, %1, %2, %3;" : "=l"(d) : "l"(a), "l"(b), "l"(c));
    return d;
}
__device__ __forceinline__ float pairsum(u64 v) {
    unsigned a, b;
    asm("mov.b64 {%0, %1}, %2;" : "=r"(a), "=r"(b) : "l"(v));
    return __uint_as_float(a) + __uint_as_float(b);
}
__device__ __forceinline__ float sigmoidf_(float x) {
    return __fdividef(1.f, 1.f + __expf(-x));
}
__device__ __forceinline__ float tanhf_(float x) {
    return __fdividef(2.f, 1.f + __expf(-2.f * x)) - 1.f;
}

// ---------------- 8-CTA batch-group barrier --------------------------------
__device__ __forceinline__ void group_barrier(int bg, unsigned target) {
    __syncthreads();
    if (threadIdx.x == 0) {
        unsigned* cnt = &g_bcount[bg * 32];
        unsigned* sen = &g_bsense[bg * 32];
        unsigned a;
        asm volatile("atom.add.acq_rel.gpu.u32 %0, [%1], 1;"
                     : "=r"(a) : "l"(cnt) : "memory");
        if (a == N_UG - 1) {
            *cnt = 0;                               // ordered by release below
            unsigned d;
            asm volatile("atom.exch.release.gpu.b32 %0, [%1], %2;"
                         : "=r"(d) : "l"(sen), "r"(target) : "memory");
        } else {
            unsigned s;
            do {
                asm volatile("ld.acquire.gpu.u32 %0, [%1];"
                             : "=r"(s) : "l"(sen) : "memory");
            } while (s != target);
        }
    }
    __syncthreads();
}

// ---------------- kernel 1: last valid index -------------------------------
__global__ void idx_kernel(const int* __restrict__ x) {
    __shared__ int m;
    int b = blockIdx.x;
    if (threadIdx.x == 0) m = T_STEPS;
    __syncthreads();
    int p = threadIdx.x;
    if (x[b * T_STEPS + p] == 0)       atomicMin(&m, p);
    if (x[b * T_STEPS + p + 256] == 0) atomicMin(&m, p + 256);
    __syncthreads();
    if (threadIdx.x == 0) g_idx[b] = m - 1;
}

// ---------------- kernel 2: persistent LSTM --------------------------------
// CTA tile: 32 units (128 gate rows) x 16 batches.
// W smem layout: Wp[kp][ridx], ridx = octet*32 + gpair*16 + uo*2 + (g&1)
//   -> thread (octet, uo) reads (i,f) pair at +0, (g,o) pair at +16;
//      8 distinct 16B addresses per warp (one crossbar phase).
__global__ void __launch_bounds__(NT, 1)
lstm_kernel(const int*   __restrict__ x,
            const float* __restrict__ emb,
            const float* __restrict__ W_ih,
            const float* __restrict__ W_hh,
            const float* __restrict__ b_ih,
            const float* __restrict__ b_hh)
{
    extern __shared__ float sm[];
    u64*   Wp = (u64*)sm;                           // [KPAIRS][WROWS] u64
    float* As = sm + KPAIRS * WROWS * 2;            // [BB_CTA][APITCH]

    const int tid = threadIdx.x;
    const int bid = blockIdx.x;
    const int ug  = bid & (N_UG - 1);
    const int bg  = bid >> 3;
    const int unit0  = ug * 32;
    const int batch0 = bg * BB_CTA;

    // ---- one-time: W slice into smem (octet-major permuted, k-pair u64) ----
    for (int e = tid; e < KPAIRS * WROWS; e += NT) {
        int kp = e >> 7, ridx = e & 127;
        int octet = ridx >> 5;
        int rem   = ridx & 31;
        int gpair = (rem >> 4) & 1;
        int uo    = (rem >> 1) & 7;
        int g     = (gpair << 1) | (rem & 1);
        int unit  = unit0 + octet * 8 + uo;
        int grow  = g * HID_D + unit;
        int k0 = kp * 2;
        float w0, w1;
        if (k0 < EMB_D) { w0 = W_ih[grow * EMB_D + k0];
                          w1 = W_ih[grow * EMB_D + k0 + 1]; }
        else            { w0 = W_hh[grow * HID_D + k0 - EMB_D];
                          w1 = W_hh[grow * HID_D + k0 - EMB_D + 1]; }
        ((float2*)Wp)[e] = make_float2(w0, w1);
    }

    // ---- thread compute tile: unit (octet, uo), batches 2p, 2p+1 -----------
    const int wid   = tid >> 5;
    const int octet = wid & 3;
    const int uo    = tid & 7;
    const int p     = (wid >> 2) * 4 + ((tid >> 3) & 3);   // 0..7
    const int bb0   = 2 * p;
    const int unit  = unit0 + octet * 8 + uo;
    const int b0g   = batch0 + bb0;
    const int b1g   = b0g + 1;

    const float bi_ = b_ih[0*HID_D + unit] + b_hh[0*HID_D + unit];
    const float bf_ = b_ih[1*HID_D + unit] + b_hh[1*HID_D + unit];
    const float bg_ = b_ih[2*HID_D + unit] + b_hh[2*HID_D + unit];
    const float bo_ = b_ih[3*HID_D + unit] + b_hh[3*HID_D + unit];
    const int idx0 = g_idx[b0g];
    const int idx1 = g_idx[b1g];
    float c0r = 0.f, c1r = 0.f;

    // ---- staging map: row = tid>>4 (0..15), part = tid&15 -------------------
    //   chunks q = part + 16*j : j=0,1 -> emb (prefetched), j=2..5 -> h
    const int srow = tid >> 4;
    const int part = tid & 15;
    const int sbatch = batch0 + srow;

    float4 pf[2];
    {
        int tok = x[sbatch * T_STEPS + 0];
        const float4* erow = (const float4*)(emb + (long long)tok * EMB_D);
        pf[0] = erow[part];
        pf[1] = erow[part + 16];
    }
    __syncthreads();

    const u64* Wth = Wp + octet * 32 + uo * 2;      // thread's W base

    for (int t = 0; t < T_STEPS; t++) {
        // ---- stage A = [emb | h_t] into smem -------------------------------
        {
            float4* dst = (float4*)(As + srow * APITCH);
            dst[part]      = pf[0];
            dst[part + 16] = pf[1];
            const float4* hrow = (const float4*)&g_hbuf[t & 1][sbatch][0];
            if (t > 0) {
                #pragma unroll
                for (int j = 2; j < 6; j++) {
                    int q = part + 16 * j;
                    dst[q] = __ldcg(hrow + (q - 32));
                }
            } else {
                float4 z = make_float4(0.f, 0.f, 0.f, 0.f);
                #pragma unroll
                for (int j = 2; j < 6; j++) dst[part + 16 * j] = z;
            }
        }
        __syncthreads();

        // ---- gate GEMM: k-pair packed FFMA2 --------------------------------
        const float* A0 = As + bb0 * APITCH;
        const float* A1 = A0 + APITCH;
        u64 ai = 0, af = 0, ag = 0, ao = 0;
        u64 bi = 0, bf = 0, bgg = 0, bo = 0;
        #pragma unroll 2
        for (int k = 0; k < K_TOT; k += 4) {
            ulonglong2 a0   = *(const ulonglong2*)(A0 + k);
            ulonglong2 a1   = *(const ulonglong2*)(A1 + k);
            const u64* wb   = Wth + (k >> 1) * WROWS;
            ulonglong2 wif0 = *(const ulonglong2*)(wb);
            ulonglong2 wgo0 = *(const ulonglong2*)(wb + 16);
            ulonglong2 wif1 = *(const ulonglong2*)(wb + WROWS);
            ulonglong2 wgo1 = *(const ulonglong2*)(wb + WROWS + 16);
            ai  = ffma2(a0.x, wif0.x, ai);   af  = ffma2(a0.x, wif0.y, af);
            ag  = ffma2(a0.x, wgo0.x, ag);   ao  = ffma2(a0.x, wgo0.y, ao);
            bi  = ffma2(a1.x, wif0.x, bi);   bf  = ffma2(a1.x, wif0.y, bf);
            bgg = ffma2(a1.x, wgo0.x, bgg);  bo  = ffma2(a1.x, wgo0.y, bo);
            ai  = ffma2(a0.y, wif1.x, ai);   af  = ffma2(a0.y, wif1.y, af);
            ag  = ffma2(a0.y, wgo1.x, ag);   ao  = ffma2(a0.y, wgo1.y, ao);
            bi  = ffma2(a1.y, wif1.x, bi);   bf  = ffma2(a1.y, wif1.y, bf);
            bgg = ffma2(a1.y, wgo1.x, bgg);  bo  = ffma2(a1.y, wgo1.y, bo);
        }

        // ---- in-register epilogue ------------------------------------------
        float* hw = &g_hbuf[(t + 1) & 1][0][0];
        {
            float gi = pairsum(ai) + bi_;
            float gf = pairsum(af) + bf_;
            float gc = pairsum(ag) + bg_;
            float go = pairsum(ao) + bo_;
            c0r = sigmoidf_(gf) * c0r + sigmoidf_(gi) * tanhf_(gc);
            float h = sigmoidf_(go) * tanhf_(c0r);
            __stcg(&hw[b0g * HID_D + unit], h);
            if (t == idx0) g_last[b0g][unit] = h;
        }
        {
            float gi = pairsum(bi) + bi_;
            float gf = pairsum(bf) + bf_;
            float gc = pairsum(bgg) + bg_;
            float go = pairsum(bo) + bo_;
            c1r = sigmoidf_(gf) * c1r + sigmoidf_(gi) * tanhf_(gc);
            float h = sigmoidf_(go) * tanhf_(c1r);
            __stcg(&hw[b1g * HID_D + unit], h);
            if (t == idx1) g_last[b1g][unit] = h;
        }

        // ---- prefetch next emb (independent of barrier) --------------------
        if (t + 1 < T_STEPS) {
            int tok = x[sbatch * T_STEPS + t + 1];
            const float4* erow = (const float4*)(emb + (long long)tok * EMB_D);
            pf[0] = erow[part];
            pf[1] = erow[part + 16];
        }

        group_barrier(bg, 1u - (t & 1u));
    }
}

// ---------------- kernel 3: logits + softmax --------------------------------
__global__ void out_kernel(const float* __restrict__ W_out,
                           const float* __restrict__ b_out,
                           float* __restrict__ out)
{
    int b = blockIdx.x, o = threadIdx.x;
    const float* h = g_last[b];
    const float* w = W_out + o * HID_D;
    float acc = b_out[o];
    for (int k = 0; k < HID_D; k += 4) {
        float4 wv = *(const float4*)(w + k);
        float4 hv = *(const float4*)(h + k);
        acc += wv.x*hv.x + wv.y*hv.y + wv.z*hv.z + wv.w*hv.w;
    }
    __shared__ float red[OUT_D];
    red[o] = acc; __syncthreads();
    for (int s = 32; s > 0; s >>= 1) {
        if (o < s) red[o] = fmaxf(red[o], red[o + s]);
        __syncthreads();
    }
    float m = red[0]; __syncthreads();
    float e = expf(acc - m);
    red[o] = e; __syncthreads();
    for (int s = 32; s > 0; s >>= 1) {
        if (o < s) red[o] += red[o + s];
        __syncthreads();
    }
    out[b * OUT_D + o] = e / red[0];
}

// ---------------- launch ----------------------------------------------------
extern "C" void kernel_launch(void* const* d_in, const int* in_sizes, int n_in,
                              void* d_out, int out_size) {
    const int*   x     = (const int*)  d_in[0];
    const float* emb   = (const float*)d_in[1];
    const float* W_ih  = (const float*)d_in[2];
    const float* W_hh  = (const float*)d_in[3];
    const float* b_ih  = (const float*)d_in[4];
    const float* b_hh  = (const float*)d_in[5];
    const float* W_out = (const float*)d_in[6];
    const float* b_out = (const float*)d_in[7];
    float* out = (float*)d_out;

    idx_kernel<<<B_SZ, 256>>>(x);

    size_t smem = (size_t)KPAIRS * WROWS * 8         // W k-pairs (192 KB)
                + (size_t)BB_CTA * APITCH * 4;       // activations (~25 KB)
    cudaFuncSetAttribute(lstm_kernel, cudaFuncAttributeMaxDynamicSharedMemorySize,
                         (int)smem);
    lstm_kernel<<<NB, NT, smem>>>(x, emb, W_ih, W_hh, b_ih, b_hh);

    out_kernel<<<B_SZ, OUT_D>>>(W_out, b_out, out);
}

// round 11
// speedup vs baseline: 1.4391x; 1.4391x over previous
#include <cuda_runtime.h>

#define T_STEPS 512
#define B_SZ    256
#define EMB_D   128
#define HID_D   256
#define OUT_D   64
#define K_TOT   384
#define KPAIRS  192            // K_TOT/2
#define NB      128            // 4 batch groups x 32 unit groups
#define NBG     32             // CTAs per batch-group barrier
#define NT      256
#define BB_CTA  64             // batches per CTA
#define APITCH  404            // pitch mod 32 == 20 -> conflict-free LDS and STS rows

typedef unsigned long long u64;

// ---------------- device scratch ------------------------------------------
__device__ float g_hbuf[2][B_SZ][HID_D];
__device__ float g_last[B_SZ][HID_D];
__device__ int   g_idx[B_SZ];
// padded barrier state: one 128B slot per group
__device__ unsigned g_bar_sense[4 * 32];  // zero-init; 512 flips -> back to 0
__device__ unsigned g_bar_count[4 * 32];

// ---------------- f32x2 helpers -------------------------------------------
__device__ __forceinline__ u64 ffma2(u64 a, u64 b, u64 c) {
    u64 d;
    asm("fma.rn.f32x2 %0, %1, %2, %3;" : "=l"(d) : "l"(a), "l"(b), "l"(c));
    return d;
}
__device__ __forceinline__ float pairsum(u64 v) {
    unsigned a, b;
    asm("mov.b64 {%0, %1}, %2;" : "=r"(a), "=r"(b) : "l"(v));
    return __uint_as_float(a) + __uint_as_float(b);
}
__device__ __forceinline__ float sigmoidf_(float x) {
    return __fdividef(1.f, 1.f + __expf(-x));
}
__device__ __forceinline__ float tanhf_(float x) {
    return __fdividef(2.f, 1.f + __expf(-2.f * x)) - 1.f;
}

// ---------------- per-batch-group grid barrier (32 CTAs) -------------------
__device__ __forceinline__ void group_barrier(int ig, unsigned target) {
    __syncthreads();
    if (threadIdx.x == 0) {
        unsigned* cnt = &g_bar_count[ig * 32];
        unsigned* sen = &g_bar_sense[ig * 32];
        unsigned a;
        asm volatile("atom.add.acq_rel.gpu.u32 %0, [%1], 1;"
                     : "=r"(a) : "l"(cnt) : "memory");
        if (a == NBG - 1) {
            *cnt = 0;                               // ordered by release below
            unsigned d;
            asm volatile("atom.exch.release.gpu.b32 %0, [%1], %2;"
                         : "=r"(d) : "l"(sen), "r"(target) : "memory");
        } else {
            unsigned s;
            do {
                asm volatile("ld.acquire.gpu.u32 %0, [%1];"
                             : "=r"(s) : "l"(sen) : "memory");
            } while (s != target);
        }
    }
    __syncthreads();
}

// ---------------- kernel 1: last valid index -------------------------------
__global__ void idx_kernel(const int* __restrict__ x) {
    __shared__ int m;
    int b = blockIdx.x;
    if (threadIdx.x == 0) m = T_STEPS;
    __syncthreads();
    int p = threadIdx.x;
    if (x[b * T_STEPS + p] == 0)       atomicMin(&m, p);
    if (x[b * T_STEPS + p + 256] == 0) atomicMin(&m, p + 256);
    __syncthreads();
    if (threadIdx.x == 0) g_idx[b] = m - 1;
}

// ---------------- kernel 2: persistent LSTM --------------------------------
__global__ void __launch_bounds__(NT, 1)
lstm_kernel(const int*   __restrict__ x,
            const float* __restrict__ emb,
            const float* __restrict__ W_ih,
            const float* __restrict__ W_hh,
            const float* __restrict__ b_ih,
            const float* __restrict__ b_hh)
{
    extern __shared__ float sm[];
    u64*   Wp = (u64*)sm;                           // [KPAIRS][32] u64 (k-pair per row)
    float* As = sm + KPAIRS * 32 * 2;               // [BB_CTA][APITCH]

    const int tid = threadIdx.x;
    const int bid = blockIdx.x;
    const int ig  = bid >> 5;                       // batch group 0..3
    const int batch0 = ig * BB_CTA;
    const int unit0  = (bid & 31) * 8;

    // --- W into smem: Wp[kp][idx]; idx = 2u + (g&1) + ((g>>1)<<4) so thread
    //     rg's two conflict-free LDS.128 give gates (i,f) and (g,o) of unit rg
    for (int e = tid; e < KPAIRS * 32; e += NT) {
        int kp = e >> 5, idx = e & 31;
        int u  = (idx >> 1) & 7;
        int g  = (idx & 1) | ((idx >> 4) << 1);
        int grow = g * HID_D + unit0 + u;
        int k0 = kp * 2;
        float w0, w1;
        if (k0 < EMB_D) { w0 = W_ih[grow * EMB_D + k0];
                          w1 = W_ih[grow * EMB_D + k0 + 1]; }
        else            { w0 = W_hh[grow * HID_D + k0 - EMB_D];
                          w1 = W_hh[grow * HID_D + k0 - EMB_D + 1]; }
        ((float2*)Wp)[e] = make_float2(w0, w1);
    }

    // thread compute tile: unit rg (4 gate rows), batches 2*bbp, 2*bbp+1
    const int rg  = tid & 7;
    const int bbp = tid >> 3;
    const int bb0 = bbp * 2;
    const int b0g = batch0 + bb0;
    const int b1g = b0g + 1;
    const int unit = unit0 + rg;

    const float bi_ = b_ih[0*HID_D + unit] + b_hh[0*HID_D + unit];
    const float bf_ = b_ih[1*HID_D + unit] + b_hh[1*HID_D + unit];
    const float bg_ = b_ih[2*HID_D + unit] + b_hh[2*HID_D + unit];
    const float bo_ = b_ih[3*HID_D + unit] + b_hh[3*HID_D + unit];
    const int idx0 = g_idx[b0g];
    const int idx1 = g_idx[b1g];
    float c0r = 0.f, c1r = 0.f;

    // staging tile: 4 threads per batch row; chunk c = part + 4*j
    //   j in [0,8)  -> c in [0,32)  : emb chunks (prefetched in registers)
    //   j in [0,16) -> c in [32,96) : h chunks
    const int sbb  = tid >> 2;
    const int part = tid & 3;
    const int srow = batch0 + sbb;

    float4 pf[8];
    {   // prefetch emb for t = 0
        int tok = x[srow * T_STEPS + 0];
        const float4* erow = (const float4*)(emb + (long long)tok * EMB_D);
        #pragma unroll
        for (int j = 0; j < 8; j++) pf[j] = erow[part + 4 * j];
    }

    for (int t = 0; t < T_STEPS; t++) {
        // ---- stage A = [emb | h_t] into smem -------------------------------
        {
            float4* dst = (float4*)(As + sbb * APITCH);
            #pragma unroll
            for (int j = 0; j < 8; j++) dst[part + 4 * j] = pf[j];
            const float4* hrow = (const float4*)&g_hbuf[t & 1][srow][0];
            if (t > 0) {
                #pragma unroll
                for (int j = 0; j < 16; j++) {
                    int c = 32 + part + 4 * j;
                    dst[c] = __ldcg(hrow + (c - 32));
                }
            } else {
                float4 z = make_float4(0.f, 0.f, 0.f, 0.f);
                #pragma unroll
                for (int j = 0; j < 16; j++) dst[32 + part + 4 * j] = z;
            }
        }
        __syncthreads();

        // ---- gate GEMM: k-pair packed FFMA2 --------------------------------
        const float* A0 = As + bb0 * APITCH;
        const float* A1 = A0 + APITCH;
        const u64*   Wr = Wp + rg * 2;
        u64 ai = 0, af = 0, ag = 0, ao = 0;
        u64 bi = 0, bf = 0, bg = 0, bo = 0;
        #pragma unroll 2
        for (int k = 0; k < K_TOT; k += 4) {
            ulonglong2 a0   = *(const ulonglong2*)(A0 + k);
            ulonglong2 a1   = *(const ulonglong2*)(A1 + k);
            const u64* wb   = Wr + k * 16;          // (k/2)*32 u64 per kpair block
            ulonglong2 wif0 = *(const ulonglong2*)(wb);
            ulonglong2 wgo0 = *(const ulonglong2*)(wb + 16);
            ulonglong2 wif1 = *(const ulonglong2*)(wb + 32);
            ulonglong2 wgo1 = *(const ulonglong2*)(wb + 48);
            ai = ffma2(a0.x, wif0.x, ai);  af = ffma2(a0.x, wif0.y, af);
            ag = ffma2(a0.x, wgo0.x, ag);  ao = ffma2(a0.x, wgo0.y, ao);
            bi = ffma2(a1.x, wif0.x, bi);  bf = ffma2(a1.x, wif0.y, bf);
            bg = ffma2(a1.x, wgo0.x, bg);  bo = ffma2(a1.x, wgo0.y, bo);
            ai = ffma2(a0.y, wif1.x, ai);  af = ffma2(a0.y, wif1.y, af);
            ag = ffma2(a0.y, wgo1.x, ag);  ao = ffma2(a0.y, wgo1.y, ao);
            bi = ffma2(a1.y, wif1.x, bi);  bf = ffma2(a1.y, wif1.y, bf);
            bg = ffma2(a1.y, wgo1.x, bg);  bo = ffma2(a1.y, wgo1.y, bo);
        }

        // ---- in-register epilogue ------------------------------------------
        float* hw = &g_hbuf[(t + 1) & 1][0][0];
        {
            float gi = pairsum(ai) + bi_;
            float gf = pairsum(af) + bf_;
            float gc = pairsum(ag) + bg_;
            float go = pairsum(ao) + bo_;
            c0r = sigmoidf_(gf) * c0r + sigmoidf_(gi) * tanhf_(gc);
            float h = sigmoidf_(go) * tanhf_(c0r);
            __stcg(&hw[b0g * HID_D + unit], h);
            if (t == idx0) g_last[b0g][unit] = h;
        }
        {
            float gi = pairsum(bi) + bi_;
            float gf = pairsum(bf) + bf_;
            float gc = pairsum(bg) + bg_;
            float go = pairsum(bo) + bo_;
            c1r = sigmoidf_(gf) * c1r + sigmoidf_(gi) * tanhf_(gc);
            float h = sigmoidf_(go) * tanhf_(c1r);
            __stcg(&hw[b1g * HID_D + unit], h);
            if (t == idx1) g_last[b1g][unit] = h;
        }

        // ---- prefetch next emb into registers (independent of barrier) -----
        if (t + 1 < T_STEPS) {
            int tok = x[srow * T_STEPS + t + 1];
            const float4* erow = (const float4*)(emb + (long long)tok * EMB_D);
            #pragma unroll
            for (int j = 0; j < 8; j++) pf[j] = erow[part + 4 * j];
        }

        group_barrier(ig, 1u - (t & 1u));
    }
}

// ---------------- kernel 3: logits + softmax --------------------------------
__global__ void out_kernel(const float* __restrict__ W_out,
                           const float* __restrict__ b_out,
                           float* __restrict__ out)
{
    int b = blockIdx.x, o = threadIdx.x;
    const float* h = g_last[b];
    const float* w = W_out + o * HID_D;
    float acc = b_out[o];
    for (int k = 0; k < HID_D; k += 4) {
        float4 wv = *(const float4*)(w + k);
        float4 hv = *(const float4*)(h + k);
        acc += wv.x*hv.x + wv.y*hv.y + wv.z*hv.z + wv.w*hv.w;
    }
    __shared__ float red[OUT_D];
    red[o] = acc; __syncthreads();
    for (int s = 32; s > 0; s >>= 1) {
        if (o < s) red[o] = fmaxf(red[o], red[o + s]);
        __syncthreads();
    }
    float m = red[0]; __syncthreads();
    float e = expf(acc - m);
    red[o] = e; __syncthreads();
    for (int s = 32; s > 0; s >>= 1) {
        if (o < s) red[o] += red[o + s];
        __syncthreads();
    }
    out[b * OUT_D + o] = e / red[0];
}

// ---------------- launch ----------------------------------------------------
extern "C" void kernel_launch(void* const* d_in, const int* in_sizes, int n_in,
                              void* d_out, int out_size) {
    const int*   x     = (const int*)  d_in[0];
    const float* emb   = (const float*)d_in[1];
    const float* W_ih  = (const float*)d_in[2];
    const float* W_hh  = (const float*)d_in[3];
    const float* b_ih  = (const float*)d_in[4];
    const float* b_hh  = (const float*)d_in[5];
    const float* W_out = (const float*)d_in[6];
    const float* b_out = (const float*)d_in[7];
    float* out = (float*)d_out;

    idx_kernel<<<B_SZ, 256>>>(x);

    size_t smem = (size_t)KPAIRS * 32 * 8            // W k-pairs (48 KB)
                + (size_t)BB_CTA * APITCH * 4;       // activations (~101 KB)
    cudaFuncSetAttribute(lstm_kernel, cudaFuncAttributeMaxDynamicSharedMemorySize,
                         (int)smem);
    lstm_kernel<<<NB, NT, smem>>>(x, emb, W_ih, W_hh, b_ih, b_hh);

    out_kernel<<<B_SZ, OUT_D>>>(W_out, b_out, out);
}

// round 17
// speedup vs baseline: 1.4642x; 1.0174x over previous
#include <cuda_runtime.h>
#include <cstdint>

#define T_STEPS 512
#define B_SZ    256
#define EMB_D   128
#define HID_D   256
#define OUT_D   64
#define K_TOT   384
#define KPAIRS  192            // K_TOT/2
#define NB      128            // 4 batch groups x 32 unit groups
#define NBG     32             // CTAs per batch-group barrier
#define NT      256
#define BB_CTA  64             // batches per CTA
#define APITCH  404            // pitch mod 32 == 20 -> conflict-free LDS and STS rows

typedef unsigned long long u64;

// ---------------- device scratch ------------------------------------------
__device__ float g_hbuf[2][B_SZ][HID_D];
__device__ float g_last[B_SZ][HID_D];
// padded barrier state: one 128B slot per group
__device__ unsigned g_bar_sense[4 * 32];  // zero-init; 512 flips -> back to 0
__device__ unsigned g_bar_count[4 * 32];

// ---------------- helpers --------------------------------------------------
__device__ __forceinline__ u64 ffma2(u64 a, u64 b, u64 c) {
    u64 d;
    asm("fma.rn.f32x2 %0, %1, %2, %3;" : "=l"(d) : "l"(a), "l"(b), "l"(c));
    return d;
}
__device__ __forceinline__ float pairsum(u64 v) {
    unsigned a, b;
    asm("mov.b64 {%0, %1}, %2;" : "=r"(a), "=r"(b) : "l"(v));
    return __uint_as_float(a) + __uint_as_float(b);
}
__device__ __forceinline__ float sigmoidf_(float x) {
    return __fdividef(1.f, 1.f + __expf(-x));
}
__device__ __forceinline__ float tanhf_(float x) {
    return __fdividef(2.f, 1.f + __expf(-2.f * x)) - 1.f;
}
__device__ __forceinline__ uint32_t smem_u32(const void* p) {
    uint32_t a;
    asm("{ .reg .u64 t; cvta.to.shared.u64 t, %1; cvt.u32.u64 %0, t; }"
        : "=r"(a) : "l"(p));
    return a;
}
__device__ __forceinline__ void cp_async16(uint32_t dst, const void* src) {
    asm volatile("cp.async.cg.shared.global [%0], [%1], 16;"
                 :: "r"(dst), "l"(src) : "memory");
}
__device__ __forceinline__ void cp_async_wait_all() {
    asm volatile("cp.async.commit_group;\n\tcp.async.wait_group 0;" ::: "memory");
}

// ---------------- per-batch-group grid barrier (32 CTAs) -------------------
__device__ __forceinline__ void group_barrier(int ig, unsigned target) {
    __syncthreads();
    if (threadIdx.x == 0) {
        unsigned* cnt = &g_bar_count[ig * 32];
        unsigned* sen = &g_bar_sense[ig * 32];
        unsigned a;
        asm volatile("atom.add.acq_rel.gpu.u32 %0, [%1], 1;"
                     : "=r"(a) : "l"(cnt) : "memory");
        if (a == NBG - 1) {
            *cnt = 0;                               // ordered by release below
            unsigned d;
            asm volatile("atom.exch.release.gpu.b32 %0, [%1], %2;"
                         : "=r"(d) : "l"(sen), "r"(target) : "memory");
        } else {
            unsigned s;
            do {
                asm volatile("ld.acquire.gpu.u32 %0, [%1];"
                             : "=r"(s) : "l"(sen) : "memory");
            } while (s != target);
        }
    }
    __syncthreads();
}

// ---------------- fused persistent kernel ----------------------------------
__global__ void __launch_bounds__(NT, 1)
lstm_fused_kernel(const int*   __restrict__ x,
                  const float* __restrict__ emb,
                  const float* __restrict__ W_ih,
                  const float* __restrict__ W_hh,
                  const float* __restrict__ b_ih,
                  const float* __restrict__ b_hh,
                  const float* __restrict__ W_out,
                  const float* __restrict__ b_out,
                  float*       __restrict__ out)
{
    extern __shared__ float sm[];
    u64*   Wp   = (u64*)sm;                         // [KPAIRS][32] u64 (k-pair rows)
    float* As   = sm + KPAIRS * 32 * 2;             // [BB_CTA][APITCH]
    int*   idxs = (int*)(As + BB_CTA * APITCH);     // [BB_CTA]

    const int tid = threadIdx.x;
    const int bid = blockIdx.x;
    const int ig  = bid >> 5;                       // batch group 0..3
    const int batch0 = ig * BB_CTA;
    const int unit0  = (bid & 31) * 8;

    // staging tile: 4 threads per batch row
    const int sbb  = tid >> 2;
    const int part = tid & 3;
    const int srow = batch0 + sbb;

    // ---- phase 0a: first-zero scan (last valid = first zero - 1) ----------
    if (tid < BB_CTA) idxs[tid] = T_STEPS;
    __syncthreads();
    {
        const int4* xr = (const int4*)(x + (long long)srow * T_STEPS) + part * 32;
        #pragma unroll 4
        for (int j = 0; j < 32; j++) {
            int4 v = xr[j];
            int p = (part * 32 + j) * 4;
            if (v.x == 0) atomicMin(&idxs[sbb], p);
            if (v.y == 0) atomicMin(&idxs[sbb], p + 1);
            if (v.z == 0) atomicMin(&idxs[sbb], p + 2);
            if (v.w == 0) atomicMin(&idxs[sbb], p + 3);
        }
    }

    // ---- phase 0b: W into smem (k-pair u64, permuted rows) -----------------
    // Wp[kp][idx]; idx = 2u + (g&1) + ((g>>1)<<4) so thread rg's two
    // conflict-free LDS.128 give gates (i,f) and (g,o) of unit rg
    for (int e = tid; e < KPAIRS * 32; e += NT) {
        int kp = e >> 5, idx = e & 31;
        int u  = (idx >> 1) & 7;
        int g  = (idx & 1) | ((idx >> 4) << 1);
        int grow = g * HID_D + unit0 + u;
        int k0 = kp * 2;
        float w0, w1;
        if (k0 < EMB_D) { w0 = W_ih[grow * EMB_D + k0];
                          w1 = W_ih[grow * EMB_D + k0 + 1]; }
        else            { w0 = W_hh[grow * HID_D + k0 - EMB_D];
                          w1 = W_hh[grow * HID_D + k0 - EMB_D + 1]; }
        ((float2*)Wp)[e] = make_float2(w0, w1);
    }

    // pre-zero the h half of A once (t==0 reads zeros; loop stays branch-lean)
    {
        float4 z = make_float4(0.f, 0.f, 0.f, 0.f);
        float4* dst = (float4*)(As + sbb * APITCH);
        #pragma unroll
        for (int j = 0; j < 16; j++) dst[32 + part + 4 * j] = z;
    }
    __syncthreads();

    // thread compute tile: unit rg (4 gate rows), batches 2*bbp, 2*bbp+1
    const int rg  = tid & 7;
    const int bbp = tid >> 3;
    const int bb0 = bbp * 2;
    const int b0g = batch0 + bb0;
    const int b1g = b0g + 1;
    const int unit = unit0 + rg;

    const float bi_ = b_ih[0*HID_D + unit] + b_hh[0*HID_D + unit];
    const float bf_ = b_ih[1*HID_D + unit] + b_hh[1*HID_D + unit];
    const float bg_ = b_ih[2*HID_D + unit] + b_hh[2*HID_D + unit];
    const float bo_ = b_ih[3*HID_D + unit] + b_hh[3*HID_D + unit];
    // last valid index = first zero - 1 (the fix: R16 omitted the -1)
    const int idx0 = idxs[bb0] - 1;
    const int idx1 = idxs[bb0 + 1] - 1;
    float c0r = 0.f, c1r = 0.f;

    const uint32_t arow_u32 = smem_u32(As) + (uint32_t)(sbb * APITCH) * 4u;

    float4 pf[8];
    {   // prefetch emb for t = 0
        int tok = x[srow * T_STEPS + 0];
        const float4* erow = (const float4*)(emb + (long long)tok * EMB_D);
        #pragma unroll
        for (int j = 0; j < 8; j++) pf[j] = erow[part + 4 * j];
    }

    for (int t = 0; t < T_STEPS; t++) {
        // ---- stage A = [emb | h_t] into smem -------------------------------
        {
            if (t > 0) {
                // h via cp.async (L2-sourced; issued before emb STS)
                const float4* hrow = (const float4*)&g_hbuf[t & 1][srow][0];
                #pragma unroll
                for (int j = 0; j < 16; j++) {
                    int c = 32 + part + 4 * j;
                    cp_async16(arow_u32 + (uint32_t)c * 16u, hrow + (c - 32));
                }
            }
            float4* dst = (float4*)(As + sbb * APITCH);
            #pragma unroll
            for (int j = 0; j < 8; j++) dst[part + 4 * j] = pf[j];
            if (t > 0) cp_async_wait_all();
        }
        __syncthreads();

        // ---- gate GEMM: k-pair packed FFMA2 --------------------------------
        const float* A0 = As + bb0 * APITCH;
        const float* A1 = A0 + APITCH;
        const u64*   Wr = Wp + rg * 2;
        u64 ai = 0, af = 0, ag = 0, ao = 0;
        u64 bi = 0, bf = 0, bg = 0, bo = 0;
        #pragma unroll 2
        for (int k = 0; k < K_TOT; k += 4) {
            ulonglong2 a0   = *(const ulonglong2*)(A0 + k);
            ulonglong2 a1   = *(const ulonglong2*)(A1 + k);
            const u64* wb   = Wr + k * 16;          // (k/2)*32 u64 per kpair block
            ulonglong2 wif0 = *(const ulonglong2*)(wb);
            ulonglong2 wgo0 = *(const ulonglong2*)(wb + 16);
            ulonglong2 wif1 = *(const ulonglong2*)(wb + 32);
            ulonglong2 wgo1 = *(const ulonglong2*)(wb + 48);
            ai = ffma2(a0.x, wif0.x, ai);  af = ffma2(a0.x, wif0.y, af);
            ag = ffma2(a0.x, wgo0.x, ag);  ao = ffma2(a0.x, wgo0.y, ao);
            bi = ffma2(a1.x, wif0.x, bi);  bf = ffma2(a1.x, wif0.y, bf);
            bg = ffma2(a1.x, wgo0.x, bg);  bo = ffma2(a1.x, wgo0.y, bo);
            ai = ffma2(a0.y, wif1.x, ai);  af = ffma2(a0.y, wif1.y, af);
            ag = ffma2(a0.y, wgo1.x, ag);  ao = ffma2(a0.y, wgo1.y, ao);
            bi = ffma2(a1.y, wif1.x, bi);  bf = ffma2(a1.y, wif1.y, bf);
            bg = ffma2(a1.y, wgo1.x, bg);  bo = ffma2(a1.y, wgo1.y, bo);
        }

        // ---- in-register epilogue ------------------------------------------
        float* hw = &g_hbuf[(t + 1) & 1][0][0];
        {
            float gi = pairsum(ai) + bi_;
            float gf = pairsum(af) + bf_;
            float gc = pairsum(ag) + bg_;
            float go = pairsum(ao) + bo_;
            c0r = sigmoidf_(gf) * c0r + sigmoidf_(gi) * tanhf_(gc);
            float h = sigmoidf_(go) * tanhf_(c0r);
            __stcg(&hw[b0g * HID_D + unit], h);
            if (t == idx0) g_last[b0g][unit] = h;
        }
        {
            float gi = pairsum(bi) + bi_;
            float gf = pairsum(bf) + bf_;
            float gc = pairsum(bg) + bg_;
            float go = pairsum(bo) + bo_;
            c1r = sigmoidf_(gf) * c1r + sigmoidf_(gi) * tanhf_(gc);
            float h = sigmoidf_(go) * tanhf_(c1r);
            __stcg(&hw[b1g * HID_D + unit], h);
            if (t == idx1) g_last[b1g][unit] = h;
        }

        // ---- prefetch next emb (overlaps barrier wait) ---------------------
        if (t + 1 < T_STEPS) {
            int tok = x[srow * T_STEPS + t + 1];
            const float4* erow = (const float4*)(emb + (long long)tok * EMB_D);
            #pragma unroll
            for (int j = 0; j < 8; j++) pf[j] = erow[part + 4 * j];
        }

        group_barrier(ig, 1u - (t & 1u));
    }

    // ---- phase 2: logits + softmax (CTA bid -> batches 2*bid, 2*bid+1) -----
    // last group_barrier ordered all g_last writes of this batch group;
    // ob = 2*bid stays inside this CTA's batch group.
    {
        const int ob  = 2 * bid + (tid >> 7);       // output batch
        const int oo  = tid & 63;                   // output index
        const bool act = ((tid >> 6) & 1) == 0;     // threads 0-63, 128-191
        float acc = 0.f, e = 0.f;
        float* red = As;                            // reuse activation smem
        if (act) {
            const float4* h4 = (const float4*)&g_last[ob][0];
            const float4* w4 = (const float4*)(W_out + oo * HID_D);
            acc = b_out[oo];
            #pragma unroll 8
            for (int k = 0; k < HID_D / 4; k++) {
                float4 wv = w4[k];
                float4 hv = __ldcg(h4 + k);
                acc += wv.x*hv.x + wv.y*hv.y + wv.z*hv.z + wv.w*hv.w;
            }
            red[(tid >> 7) * 64 + oo] = acc;
        }
        __syncthreads();
        if (act) {
            const float* r = red + (tid >> 7) * 64;
            float m = r[0];
            #pragma unroll
            for (int j = 1; j < 64; j++) m = fmaxf(m, r[j]);
            e = expf(acc - m);
            red[128 + (tid >> 7) * 64 + oo] = e;
        }
        __syncthreads();
        if (act) {
            const float* r = red + 128 + (tid >> 7) * 64;
            float s = 0.f;
            #pragma unroll
            for (int j = 0; j < 64; j++) s += r[j];
            out[ob * OUT_D + oo] = e / s;
        }
    }
}

// ---------------- launch ----------------------------------------------------
extern "C" void kernel_launch(void* const* d_in, const int* in_sizes, int n_in,
                              void* d_out, int out_size) {
    const int*   x     = (const int*)  d_in[0];
    const float* emb   = (const float*)d_in[1];
    const float* W_ih  = (const float*)d_in[2];
    const float* W_hh  = (const float*)d_in[3];
    const float* b_ih  = (const float*)d_in[4];
    const float* b_hh  = (const float*)d_in[5];
    const float* W_out = (const float*)d_in[6];
    const float* b_out = (const float*)d_in[7];
    float* out = (float*)d_out;

    size_t smem = (size_t)KPAIRS * 32 * 8            // W k-pairs (48 KB)
                + (size_t)BB_CTA * APITCH * 4        // activations (~101 KB)
                + (size_t)BB_CTA * 4;                // idx scratch
    cudaFuncSetAttribute(lstm_fused_kernel,
                         cudaFuncAttributeMaxDynamicSharedMemorySize, (int)smem);
    lstm_fused_kernel<<<NB, NT, smem>>>(x, emb, W_ih, W_hh, b_ih, b_hh,
                                        W_out, b_out, out);
}